// round 2
// baseline (speedup 1.0000x reference)
#include <cuda_runtime.h>
#include <cstddef>

// RNN_22883585753135: 2-layer tanh RNN
//   B=64, T=4096, IN=H=128
//   out = concat( out1[B,T,H], h_n[2,B,H] )
//
// Phases (default stream, graph-capturable, allocation-free):
//   1. gemm_xw: xp0 = x    @ W_ih0^T + (b_ih0+b_hh0)  -> g_xp
//   2. rnn_rec: layer-0 scan, reads g_xp, writes out0 -> g_buf, h0_n -> tail
//   3. gemm_xw: xp1 = out0 @ W_ih1^T + (b_ih1+b_hh1)  -> g_xp  (reuse)
//   4. rnn_rec: layer-1 scan, reads g_xp, writes out1 -> d_out, h1_n -> tail

typedef unsigned long long ull;

#define BB 64
#define TT 4096
#define HH 128
#define BT (BB * TT)

// Scratch via __device__ globals (allocation-free rule). g_xp padded by 8
// rows so the recurrence prefetch ring can read past the last row safely.
__device__ __align__(16) float g_xp[(size_t)(BT + 8) * HH];
__device__ __align__(16) float g_buf[(size_t)BT * HH];

// ---------------- packed f32x2 helpers (sm_100+) ----------------
__device__ __forceinline__ ull fma2(ull a, ull b, ull c) {
    ull d;
    asm("fma.rn.f32x2 %0, %1, %2, %3;" : "=l"(d) : "l"(a), "l"(b), "l"(c));
    return d;
}
__device__ __forceinline__ ull add2(ull a, ull b) {
    ull d;
    asm("add.rn.f32x2 %0, %1, %2;" : "=l"(d) : "l"(a), "l"(b));
    return d;
}
__device__ __forceinline__ float2 unpack2(ull v) {
    float2 f;
    asm("mov.b64 {%0, %1}, %2;" : "=f"(f.x), "=f"(f.y) : "l"(v));
    return f;
}

// Accurate tanh (~1e-7 rel): tanh(|x|) = (e^{2|x|}-1)/(e^{2|x|}+1)
__device__ __forceinline__ float tanh_fast(float x) {
    float ax = fminf(fabsf(x), 15.0f);
    float e  = __expf(2.0f * ax);
    float r  = __fdividef(e - 1.0f, e + 1.0f);
    return copysignf(r, x);
}

// ---------------- GEMM: out[m][n] = sum_k A[m,k]*W[n,k] + b0[n]+b1[n] ----
// M = BT, N = 128, K = 128. Tile: 64 rows x 128 cols per block, 256 threads,
// thread micro-tile 4x8. Smem k2-major so the inner-loop LDS is broadcast /
// conflict-free. Packed f32x2 FMAs -> 128 MAC/cyc/SM issue peak.

#define AS_STRIDE 66    // 64 rows + pad (float2 units)
#define WS_STRIDE 130   // 128 cols + pad (float2 units)
#define GEMM_SMEM_ULL (64 * AS_STRIDE + 64 * WS_STRIDE)
#define GEMM_SMEM_BYTES (GEMM_SMEM_ULL * 8)   // 100,352 B < 228 KB carveout

__global__ void __launch_bounds__(256, 1) gemm_xw(
    const float* __restrict__ A, const float* __restrict__ W,
    const float* __restrict__ b0, const float* __restrict__ b1,
    float* __restrict__ out)
{
    extern __shared__ ull sm[];
    ull* As = sm;                    // [k2][row]  : 64 x 66
    ull* Ws = sm + 64 * AS_STRIDE;   // [k2][col]  : 64 x 130

    const int tid = threadIdx.x;
    const size_t m0 = (size_t)blockIdx.x * 64;

    // A tile (64 rows x 128 k) -> k2-major. Coalesced 8B global reads.
    const ull* Ag = (const ull*)(A + m0 * HH);
    #pragma unroll
    for (int i = 0; i < 16; i++) {
        int idx = tid + i * 256;            // 0..4095
        int r = idx >> 6, k2 = idx & 63;
        As[k2 * AS_STRIDE + r] = Ag[(size_t)r * 64 + k2];
    }
    // Full W (128 x 128) -> k2-major.
    const ull* Wg = (const ull*)W;
    #pragma unroll
    for (int i = 0; i < 32; i++) {
        int idx = tid + i * 256;            // 0..8191
        int n = idx >> 6, k2 = idx & 63;
        Ws[k2 * WS_STRIDE + n] = Wg[n * 64 + k2];
    }
    __syncthreads();

    const int tx = tid & 15;     // col group: cols tx + 16*c
    const int ty = tid >> 4;     // row group: rows ty*4 + r
    ull acc[4][8];
    #pragma unroll
    for (int r = 0; r < 4; r++)
        #pragma unroll
        for (int c = 0; c < 8; c++) acc[r][c] = 0ull;

    #pragma unroll 4
    for (int k2 = 0; k2 < 64; k2++) {
        ull a2[4], w2[8];
        #pragma unroll
        for (int r = 0; r < 4; r++) a2[r] = As[k2 * AS_STRIDE + ty * 4 + r];
        #pragma unroll
        for (int c = 0; c < 8; c++) w2[c] = Ws[k2 * WS_STRIDE + tx + 16 * c];
        #pragma unroll
        for (int r = 0; r < 4; r++)
            #pragma unroll
            for (int c = 0; c < 8; c++)
                acc[r][c] = fma2(a2[r], w2[c], acc[r][c]);
    }

    float bias[8];
    #pragma unroll
    for (int c = 0; c < 8; c++) {
        int n = tx + 16 * c;
        bias[c] = __ldg(b0 + n) + __ldg(b1 + n);
    }
    #pragma unroll
    for (int r = 0; r < 4; r++) {
        size_t row = m0 + ty * 4 + r;
        #pragma unroll
        for (int c = 0; c < 8; c++) {
            float2 v = unpack2(acc[r][c]);
            out[row * HH + tx + 16 * c] = v.x + v.y + bias[c];
        }
    }
}

// ---------------- Recurrence: one CTA per batch row ----------------
// 128 threads; thread j owns output neuron j and keeps W_hh row j (128
// floats) in registers as 64 packed f32x2. h double-buffered in smem, read
// back as LDS.128 broadcasts. xp streamed with an 8-deep register prefetch
// ring (covers DRAM latency across the per-step barriers).

__global__ void __launch_bounds__(128, 1) rnn_rec(
    const float* __restrict__ xp, const float* __restrict__ Whh,
    float* __restrict__ out, float* __restrict__ hN)
{
    const int b = blockIdx.x;
    const int j = threadIdx.x;

    __shared__ __align__(16) float hs[2][HH];

    // W_hh row j -> registers (64 packed pairs)
    ull w[64];
    const ull* wg = (const ull*)(Whh + j * HH);
    #pragma unroll
    for (int i = 0; i < 64; i++) w[i] = wg[i];

    hs[0][j] = 0.0f;   // h0 = 0
    hs[1][j] = 0.0f;

    const float* p  = xp  + (size_t)b * TT * HH + j;
    float*       po = out + (size_t)b * TT * HH + j;

    float xr[8];
    #pragma unroll
    for (int i = 0; i < 8; i++) xr[i] = __ldg(p + i * HH);

    __syncthreads();

    for (int t = 0; t < TT; t += 8) {
        #pragma unroll
        for (int s = 0; s < 8; s++) {
            float xv = xr[s];
            // prefetch 8 steps ahead (g_xp padded; for b<63 this reads the
            // next batch's rows, which is valid memory)
            xr[s] = __ldg(p + (size_t)(t + s + 8) * HH);

            const ulonglong2* hv = (const ulonglong2*)hs[s & 1];
            ull a0 = 0ull, a1 = 0ull, a2c = 0ull, a3 = 0ull;
            #pragma unroll
            for (int k = 0; k < 32; k += 2) {
                ulonglong2 h01 = hv[k];
                ulonglong2 h23 = hv[k + 1];
                a0  = fma2(h01.x, w[2 * k],     a0);
                a1  = fma2(h01.y, w[2 * k + 1], a1);
                a2c = fma2(h23.x, w[2 * k + 2], a2c);
                a3  = fma2(h23.y, w[2 * k + 3], a3);
            }
            ull s0 = add2(a0, a2c);
            ull s1 = add2(a1, a3);
            float2 sv = unpack2(add2(s0, s1));
            float pre = sv.x + sv.y + xv;
            float hn = tanh_fast(pre);

            po[(size_t)(t + s) * HH] = hn;     // coalesced 512B store/warp
            hs[(s + 1) & 1][j] = hn;
            __syncthreads();
        }
    }
    // final state lives in hs[0] (last step of last block wrote (7+1)&1 = 0)
    hN[b * HH + j] = hs[0][j];
}

// ---------------- launch ----------------
extern "C" void kernel_launch(void* const* d_in, const int* in_sizes, int n_in,
                              void* d_out, int out_size)
{
    const float* x     = (const float*)d_in[0];
    const float* W_ih0 = (const float*)d_in[1];
    const float* W_hh0 = (const float*)d_in[2];
    const float* b_ih0 = (const float*)d_in[3];
    const float* b_hh0 = (const float*)d_in[4];
    const float* W_ih1 = (const float*)d_in[5];
    const float* W_hh1 = (const float*)d_in[6];
    const float* b_ih1 = (const float*)d_in[7];
    const float* b_hh1 = (const float*)d_in[8];

    float* out1 = (float*)d_out;                       // [B,T,H]
    float* hN   = out1 + (size_t)BT * HH;              // [2,B,H]

    void *xp_p = nullptr, *buf_p = nullptr;
    cudaGetSymbolAddress(&xp_p, g_xp);
    cudaGetSymbolAddress(&buf_p, g_buf);
    float* xp  = (float*)xp_p;
    float* buf = (float*)buf_p;

    static int smem_set = 0;
    if (!smem_set) {
        cudaFuncSetAttribute(gemm_xw,
                             cudaFuncAttributeMaxDynamicSharedMemorySize,
                             GEMM_SMEM_BYTES);
        smem_set = 1;
    }

    dim3 ggrid(BT / 64), gblk(256);
    dim3 rgrid(BB), rblk(HH);

    // layer 0
    gemm_xw<<<ggrid, gblk, GEMM_SMEM_BYTES>>>(x, W_ih0, b_ih0, b_hh0, xp);
    rnn_rec<<<rgrid, rblk>>>(xp, W_hh0, buf, hN);              // h0_n
    // layer 1
    gemm_xw<<<ggrid, gblk, GEMM_SMEM_BYTES>>>(buf, W_ih1, b_ih1, b_hh1, xp);
    rnn_rec<<<rgrid, rblk>>>(xp, W_hh1, out1, hN + BB * HH);   // h1_n
}